// round 1
// baseline (speedup 1.0000x reference)
#include <cuda_runtime.h>
#include <math.h>

#define BB 256
#define TT 512
#define KK 128

// Scratch (allocation-free rule: __device__ globals).
__device__ unsigned char g_bp[(size_t)BB * TT * KK];   // backpointers, 16.8 MB
__device__ float g_nll[BB];

// Dynamic smem layout:
//   [0, 65536)        float s_mat[128*128]  : trans (viterbi) or exp(trans) (lse);
//                     reused after forward as bp cache (viterbi)
//   [65536, 66048)    float s_vec[128]      : alpha broadcast / p vector
//   [66048, 66304)    float s_red[64]       : reduction scratch (vals + idx)
#define SMEM_BYTES (65536 + 512 + 256)

extern "C" __global__ void __launch_bounds__(128, 3) crf_fwd(
    const float* __restrict__ logits,
    const int*   __restrict__ labels,
    const int*   __restrict__ seq_lens,
    const float* __restrict__ trans,
    float* __restrict__ out)
{
    extern __shared__ char smem_raw[];
    float* s_mat = (float*)smem_raw;                  // 16384 floats
    float* s_vec = (float*)(smem_raw + 65536);        // 128 floats
    float* s_red = (float*)(smem_raw + 66048);        // 64 floats
    int*   s_redi = (int*)s_red;

    const int tid = threadIdx.x;
    const bool is_vit = (blockIdx.x < BB);
    const int b = is_vit ? blockIdx.x : (blockIdx.x - BB);
    const int len = seq_lens[b];
    const float* lgb = logits + (size_t)b * TT * KK;

    // Load the KxK matrix into smem (trans for Viterbi CTAs, exp(trans) for LSE CTAs)
    for (int idx = tid; idx < KK * KK; idx += 128) {
        float v = trans[idx];
        s_mat[idx] = is_vit ? v : __expf(v);
    }
    float alpha = lgb[tid];   // alpha0 = logits[b,0,tid]
    __syncthreads();

    if (is_vit) {
        // ---------------- Viterbi forward ----------------
        for (int t = 1; t < len; ++t) {
            s_vec[tid] = alpha;
            __syncthreads();
            float best = -INFINITY;
            int   bi = 0;
            #pragma unroll 8
            for (int i = 0; i < KK; ++i) {
                float s = s_vec[i] + s_mat[i * KK + tid];
                if (s > best) { best = s; bi = i; }   // strict > keeps FIRST argmax (jnp.argmax)
            }
            alpha = best + lgb[t * KK + tid];
            g_bp[((size_t)b * TT + t) * KK + tid] = (unsigned char)bi;
            __syncthreads();
        }
        // argmax over final alpha, first-index tie break
        {
            float v = alpha; int idx = tid;
            #pragma unroll
            for (int m = 16; m > 0; m >>= 1) {
                float ov = __shfl_xor_sync(0xFFFFFFFFu, v, m);
                int   oi = __shfl_xor_sync(0xFFFFFFFFu, idx, m);
                if (ov > v || (ov == v && oi < idx)) { v = ov; idx = oi; }
            }
            if ((tid & 31) == 0) { s_red[tid >> 5] = v; s_redi[8 + (tid >> 5)] = idx; }
        }
        __syncthreads();
        int last;
        {
            float bv = s_red[0]; int bidx = s_redi[8];
            #pragma unroll
            for (int w = 1; w < 4; ++w) {
                float wv = s_red[w]; int wi = s_redi[8 + w];
                if (wv > bv || (wv == bv && wi < bidx)) { bv = wv; bidx = wi; }
            }
            last = bidx;
        }
        __syncthreads();   // everyone done with s_mat (trans) -> reuse as bp cache

        // Pull this batch's backpointer rows (t=1..len-1) into smem, then chase in smem.
        unsigned char* s_bp = (unsigned char*)s_mat;
        {
            const int nbytes = (len - 1) * KK;        // multiple of 16, <= 65408
            const int4* src = (const int4*)&g_bp[((size_t)b * TT + 1) * KK];
            int4* dst = (int4*)s_bp;
            for (int i = tid; i * 16 < nbytes; i += 128) dst[i] = src[i];
        }
        __syncthreads();
        if (tid == 0) {
            float* pred = out + 1 + (size_t)b * TT;
            int tag = last;
            // positions len-1 .. T-1 all decode to `last` (identity bps in masked region)
            for (int t = TT - 1; t >= len - 1; --t) pred[t] = (float)tag;
            for (int t = len - 1; t >= 1; --t) {
                tag = s_bp[(t - 1) * KK + tag];
                pred[t - 1] = (float)tag;
            }
        }
    } else {
        // ---------------- CRF log-norm forward (matvec form) ----------------
        for (int t = 1; t < len; ++t) {
            float v = alpha;
            #pragma unroll
            for (int m = 16; m > 0; m >>= 1) v = fmaxf(v, __shfl_xor_sync(0xFFFFFFFFu, v, m));
            if ((tid & 31) == 0) s_red[tid >> 5] = v;
            __syncthreads();
            float M = fmaxf(fmaxf(s_red[0], s_red[1]), fmaxf(s_red[2], s_red[3]));
            s_vec[tid] = __expf(alpha - M);
            __syncthreads();
            float dot = 0.f;
            #pragma unroll 8
            for (int i = 0; i < KK; ++i) dot = fmaf(s_vec[i], s_mat[i * KK + tid], dot);
            alpha = __logf(dot) + M + lgb[t * KK + tid];
            __syncthreads();
        }
        // logZ = logsumexp(alpha) (deterministic fixed-order reduction)
        float v = alpha;
        #pragma unroll
        for (int m = 16; m > 0; m >>= 1) v = fmaxf(v, __shfl_xor_sync(0xFFFFFFFFu, v, m));
        if ((tid & 31) == 0) s_red[tid >> 5] = v;
        __syncthreads();
        float M = fmaxf(fmaxf(s_red[0], s_red[1]), fmaxf(s_red[2], s_red[3]));
        float e = __expf(alpha - M);
        #pragma unroll
        for (int m = 16; m > 0; m >>= 1) e += __shfl_xor_sync(0xFFFFFFFFu, e, m);
        if ((tid & 31) == 0) s_red[8 + (tid >> 5)] = e;
        __syncthreads();
        float logZ = __logf(s_red[8] + s_red[9] + s_red[10] + s_red[11]) + M;

        // ---------------- sequence score ----------------
        const int* lab = labels + b * TT;
        float sc = 0.f;
        for (int t = tid; t < len; t += 128) {
            int l = lab[t];
            sc += lgb[t * KK + l];
            if (t >= 1) sc += trans[lab[t - 1] * KK + l];
        }
        #pragma unroll
        for (int m = 16; m > 0; m >>= 1) sc += __shfl_xor_sync(0xFFFFFFFFu, sc, m);
        __syncthreads();
        if ((tid & 31) == 0) s_red[tid >> 5] = sc;
        __syncthreads();
        if (tid == 0) g_nll[b] = logZ - (s_red[0] + s_red[1] + s_red[2] + s_red[3]);
    }
}

// Deterministic final reduction: loss = sum_b nll[b]
extern "C" __global__ void crf_loss(float* __restrict__ out)
{
    __shared__ float s[BB];
    int tid = threadIdx.x;
    s[tid] = g_nll[tid];
    __syncthreads();
    for (int m = BB / 2; m > 0; m >>= 1) {
        if (tid < m) s[tid] += s[tid + m];
        __syncthreads();
    }
    if (tid == 0) out[0] = s[0];
}

extern "C" void kernel_launch(void* const* d_in, const int* in_sizes, int n_in,
                              void* d_out, int out_size)
{
    const float* logits   = (const float*)d_in[0];
    const int*   labels   = (const int*)d_in[1];
    const int*   seq_lens = (const int*)d_in[2];
    const float* trans    = (const float*)d_in[3];
    float* out = (float*)d_out;

    // Idempotent, called every launch (no static guards).
    cudaFuncSetAttribute(crf_fwd, cudaFuncAttributeMaxDynamicSharedMemorySize, SMEM_BYTES);

    crf_fwd<<<2 * BB, 128, SMEM_BYTES>>>(logits, labels, seq_lens, trans, out);
    crf_loss<<<1, BB>>>(out);
}

// round 2
// speedup vs baseline: 1.5142x; 1.5142x over previous
#include <cuda_runtime.h>
#include <math.h>

#define BB 256
#define TT 512
#define KK 128

// Scratch (allocation-free rule: __device__ globals).
__device__ unsigned char g_bp[(size_t)BB * TT * KK];   // backpointers, 16.8 MB
__device__ float g_nll[BB];
__device__ int   g_order[BB];

// Dynamic smem layout (bytes):
//   [0, 67584)        s_mat : Viterbi = trans row-major [i][j] (64KB, reused as bp cache)
//                             LSE     = exp(trans) TRANSPOSED, padded rows of 132 floats
//   [67584, 68096)    s_vec : 128 floats (LSE p vector)
//   [68096, 69120)    s_cand: 4 warps x 32 uint2 candidate entries (alpha bits, index)
//   [69120, 69136)    s_wmax: 4 floats (per-warp max)
//   [69136, 69152)    s_wcnt: 4 ints  (per-warp candidate count)
//   [69152, 69216)    s_red : 64B reduce scratch
#define OFF_VEC   67584
#define OFF_CAND  68096
#define OFF_WMAX  69120
#define OFF_WCNT  69136
#define OFF_RED   69152
#define SMEM_BYTES 69632

// Descending-length rank: g_order[rank] = batch index. Deterministic O(B^2).
extern "C" __global__ void sort_order(const int* __restrict__ seq_lens)
{
    __shared__ int lens[BB];
    int b = threadIdx.x;
    lens[b] = seq_lens[b];
    __syncthreads();
    int my = lens[b];
    int r = 0;
    for (int j = 0; j < BB; ++j) {
        int lj = lens[j];
        r += (lj > my) || (lj == my && j < b);
    }
    g_order[r] = b;
}

extern "C" __global__ void __launch_bounds__(128, 3) crf_fwd(
    const float* __restrict__ logits,
    const int*   __restrict__ labels,
    const int*   __restrict__ seq_lens,
    const float* __restrict__ trans,
    float* __restrict__ out)
{
    extern __shared__ char smem_raw[];
    float* s_mat  = (float*)smem_raw;
    float* s_vec  = (float*)(smem_raw + OFF_VEC);
    uint2* s_cand = (uint2*)(smem_raw + OFF_CAND);
    float* s_wmax = (float*)(smem_raw + OFF_WMAX);
    int*   s_wcnt = (int*)  (smem_raw + OFF_WCNT);
    float* s_red  = (float*)(smem_raw + OFF_RED);
    int*   s_redi = (int*)s_red;

    const int tid  = threadIdx.x;
    const int lane = tid & 31;
    const int wid  = tid >> 5;
    const bool is_vit = (blockIdx.x & 1) == 0;   // interleave kinds in launch order
    const int b   = g_order[blockIdx.x >> 1];    // longest sequences first
    const int len = seq_lens[b];
    const float* lgb = logits + (size_t)b * TT * KK;

    if (is_vit) {
        for (int idx = tid; idx < KK * KK; idx += 128) s_mat[idx] = trans[idx];
    } else {
        // transposed exp(trans), padded rows (132 floats) for conflict-free LDS.128
        for (int idx = tid; idx < KK * KK; idx += 128) {
            int i = idx >> 7, j = idx & 127;
            s_mat[j * 132 + i] = __expf(trans[idx]);
        }
    }
    float alpha = lgb[tid];   // alpha0
    __syncthreads();

    if (is_vit) {
        // ---------------- Viterbi forward with exact candidate pruning ----------------
        unsigned char* bp_out = &g_bp[(size_t)b * TT * KK];
        for (int t = 1; t < len; ++t) {
            float emit = __ldg(&lgb[t * KK + tid]);   // prefetch emission
            // per-warp max of alpha
            float wm = alpha;
            #pragma unroll
            for (int m = 16; m > 0; m >>= 1) wm = fmaxf(wm, __shfl_xor_sync(0xFFFFFFFFu, wm, m));
            if (lane == 0) s_wmax[wid] = wm;
            __syncthreads();
            float amax = fmaxf(fmaxf(s_wmax[0], s_wmax[1]), fmaxf(s_wmax[2], s_wmax[3]));
            // trans in [0,1): states with alpha <= amax-1 are dominated. margin > ulp(|alpha|max).
            bool keep = alpha >= amax - 1.002f;
            unsigned mask = __ballot_sync(0xFFFFFFFFu, keep);
            if (keep) {
                int pos = __popc(mask & ((1u << lane) - 1u));
                s_cand[wid * 32 + pos] = make_uint2(__float_as_uint(alpha), (unsigned)tid);
            }
            if (lane == 0) s_wcnt[wid] = __popc(mask);
            __syncthreads();
            float best = -INFINITY;
            int   bi = 0;
            #pragma unroll
            for (int w = 0; w < 4; ++w) {
                int cnt = s_wcnt[w];
                const uint2* lst = &s_cand[w * 32];
                for (int c = 0; c < cnt; ++c) {        // ascending i: first-argmax kept by strict >
                    uint2 e = lst[c];
                    float s = __uint_as_float(e.x) + s_mat[e.y * KK + tid];
                    if (s > best) { best = s; bi = (int)e.y; }
                }
            }
            alpha = best + emit;
            bp_out[t * KK + tid] = (unsigned char)bi;
        }
        // argmax over final alpha, first-index tie break
        {
            float v = alpha; int idx = tid;
            #pragma unroll
            for (int m = 16; m > 0; m >>= 1) {
                float ov = __shfl_xor_sync(0xFFFFFFFFu, v, m);
                int   oi = __shfl_xor_sync(0xFFFFFFFFu, idx, m);
                if (ov > v || (ov == v && oi < idx)) { v = ov; idx = oi; }
            }
            if (lane == 0) { s_red[wid] = v; s_redi[8 + wid] = idx; }
        }
        __syncthreads();
        int last;
        {
            float bv = s_red[0]; int bidx = s_redi[8];
            #pragma unroll
            for (int w = 1; w < 4; ++w) {
                float wv = s_red[w]; int wi = s_redi[8 + w];
                if (wv > bv || (wv == bv && wi < bidx)) { bv = wv; bidx = wi; }
            }
            last = bidx;
        }
        __syncthreads();   // everyone done with s_mat -> reuse as bp cache

        unsigned char* s_bp = (unsigned char*)s_mat;
        {
            const int nbytes = (len - 1) * KK;        // multiple of 16, <= 65408
            const int4* src = (const int4*)&g_bp[((size_t)b * TT + 1) * KK];
            int4* dst = (int4*)s_bp;
            for (int i = tid; i * 16 < nbytes; i += 128) dst[i] = src[i];
        }
        __syncthreads();
        if (tid == 0) {
            float* pred = out + 1 + (size_t)b * TT;
            int tag = last;
            for (int t = TT - 1; t >= len - 1; --t) pred[t] = (float)tag;
            for (int t = len - 1; t >= 1; --t) {
                tag = s_bp[(t - 1) * KK + tag];
                pred[t - 1] = (float)tag;
            }
        }
    } else {
        // ---------------- CRF log-norm forward (vectorized matvec) ----------------
        const float4* mrow = (const float4*)(s_mat + tid * 132);   // 528B rows: 16B aligned
        for (int t = 1; t < len; ++t) {
            float emit = __ldg(&lgb[t * KK + tid]);
            float wm = alpha;
            #pragma unroll
            for (int m = 16; m > 0; m >>= 1) wm = fmaxf(wm, __shfl_xor_sync(0xFFFFFFFFu, wm, m));
            if (lane == 0) s_wmax[wid] = wm;
            __syncthreads();
            float M = fmaxf(fmaxf(s_wmax[0], s_wmax[1]), fmaxf(s_wmax[2], s_wmax[3]));
            s_vec[tid] = __expf(alpha - M);
            __syncthreads();
            float a0 = 0.f, a1 = 0.f, a2 = 0.f, a3 = 0.f;
            const float4* pv = (const float4*)s_vec;
            #pragma unroll 8
            for (int q = 0; q < 32; ++q) {
                float4 mq = mrow[q];
                float4 p  = pv[q];
                a0 = fmaf(p.x, mq.x, a0);
                a1 = fmaf(p.y, mq.y, a1);
                a2 = fmaf(p.z, mq.z, a2);
                a3 = fmaf(p.w, mq.w, a3);
            }
            float dot = (a0 + a1) + (a2 + a3);
            alpha = __logf(dot) + M + emit;
        }
        // logZ = logsumexp(alpha), deterministic fixed-order reduction
        float v = alpha;
        #pragma unroll
        for (int m = 16; m > 0; m >>= 1) v = fmaxf(v, __shfl_xor_sync(0xFFFFFFFFu, v, m));
        if (lane == 0) s_red[wid] = v;
        __syncthreads();
        float M = fmaxf(fmaxf(s_red[0], s_red[1]), fmaxf(s_red[2], s_red[3]));
        float e = __expf(alpha - M);
        #pragma unroll
        for (int m = 16; m > 0; m >>= 1) e += __shfl_xor_sync(0xFFFFFFFFu, e, m);
        if (lane == 0) s_red[8 + wid] = e;
        __syncthreads();
        float logZ = __logf(s_red[8] + s_red[9] + s_red[10] + s_red[11]) + M;

        // sequence score
        const int* lab = labels + b * TT;
        float sc = 0.f;
        for (int t = tid; t < len; t += 128) {
            int l = lab[t];
            sc += lgb[t * KK + l];
            if (t >= 1) sc += trans[lab[t - 1] * KK + l];
        }
        #pragma unroll
        for (int m = 16; m > 0; m >>= 1) sc += __shfl_xor_sync(0xFFFFFFFFu, sc, m);
        __syncthreads();
        if (lane == 0) s_red[wid] = sc;
        __syncthreads();
        if (tid == 0) g_nll[b] = logZ - (s_red[0] + s_red[1] + s_red[2] + s_red[3]);
    }
}

// Deterministic final reduction: loss = sum_b nll[b]
extern "C" __global__ void crf_loss(float* __restrict__ out)
{
    __shared__ float s[BB];
    int tid = threadIdx.x;
    s[tid] = g_nll[tid];
    __syncthreads();
    for (int m = BB / 2; m > 0; m >>= 1) {
        if (tid < m) s[tid] += s[tid + m];
        __syncthreads();
    }
    if (tid == 0) out[0] = s[0];
}

extern "C" void kernel_launch(void* const* d_in, const int* in_sizes, int n_in,
                              void* d_out, int out_size)
{
    const float* logits   = (const float*)d_in[0];
    const int*   labels   = (const int*)d_in[1];
    const int*   seq_lens = (const int*)d_in[2];
    const float* trans    = (const float*)d_in[3];
    float* out = (float*)d_out;

    cudaFuncSetAttribute(crf_fwd, cudaFuncAttributeMaxDynamicSharedMemorySize, SMEM_BYTES);

    sort_order<<<1, BB>>>(seq_lens);
    crf_fwd<<<2 * BB, 128, SMEM_BYTES>>>(logits, labels, seq_lens, trans, out);
    crf_loss<<<1, BB>>>(out);
}